// round 8
// baseline (speedup 1.0000x reference)
#include <cuda_runtime.h>
#include <cuda_fp16.h>

#define NN 200000
#define EE 400000
#define DD 128
#define LL 5
#define BN_EPS 1e-5f

#define AS 132                         // padded smem stride (words)
#define GEMM_SMEM ((64 * AS + 128 * AS) * 4)
#define MSG_BLOCKS 1184
#define SCAN_BLK 512
#define SCAN_NBLK ((NN + SCAN_BLK - 1) / SCAN_BLK)   // 391

// ---------------- scratch (static device globals; no allocation) ----------------
__device__ float  g_h[(size_t)NN * DD];       // h0 (layer-0 input)
__device__ __half g_hl16[(size_t)NN * DD];    // linear output (fp16)
__device__ float  g_agg[(size_t)NN * DD];     // pre-BN layer output
__device__ float  g_hbuf[(size_t)4 * NN * DD]; // post-BN h1..h4 for final total
__device__ __half g_ee16[(size_t)EE * DD];    // edge embeddings (dest-sorted, fp16)
__device__ float  g_norm[EE];                 // dest-sorted
__device__ int    g_rows[EE];                 // dest-sorted src
__device__ int    g_perm[EE];
__device__ int    g_cnt[NN];
__device__ int    g_off[NN + 1];
__device__ int    g_cursor[NN];
__device__ int    g_bsum[SCAN_BLK];
__device__ float  g_deg[NN];
__device__ float  g_dis[NN];
__device__ float  g_invdeg[NN];
__device__ double g_sum[DD];
__device__ double g_sq[DD];
__device__ float  g_scale[DD];
__device__ float  g_shift[DD];

// ---------------- encoders / setup ----------------
__global__ void k_node_enc(const int* __restrict__ x,
                           const float* __restrict__ at,
                           float* __restrict__ out) {
    int node = blockIdx.x * 8 + (threadIdx.x >> 5);
    if (node >= NN) return;
    int lane = threadIdx.x & 31;
    float4 acc = make_float4(0.f, 0.f, 0.f, 0.f);
#pragma unroll
    for (int c = 0; c < 9; c++) {
        int idx = x[node * 9 + c];
        const float4* t = (const float4*)(at + ((size_t)c * 100 + idx) * DD);
        float4 v = t[lane];
        acc.x += v.x; acc.y += v.y; acc.z += v.z; acc.w += v.w;
    }
    size_t o = (size_t)node * 32 + lane;
    ((float4*)g_h)[o] = acc;
    ((float4*)out)[o] = acc;
}

__global__ void k_deg_init() {
    int i = blockIdx.x * blockDim.x + threadIdx.x;
    if (i < NN) { g_deg[i] = 1.0f; g_cnt[i] = 0; }
}

__global__ void k_deg_count(const int* __restrict__ ei) {
    int e = blockIdx.x * blockDim.x + threadIdx.x;
    if (e < EE) {
        atomicAdd(&g_deg[ei[e]], 1.0f);        // by source (degree)
        atomicAdd(&g_cnt[ei[EE + e]], 1);      // by dest (sort histogram)
    }
}

__global__ void k_dis() {
    int i = blockIdx.x * blockDim.x + threadIdx.x;
    if (i < NN) {
        float d = g_deg[i];
        g_dis[i] = rsqrtf(d);
        g_invdeg[i] = 1.0f / d;
    }
}

// ---- 2-level exclusive scan of g_cnt -> g_off ----
__global__ void k_scan1() {
    __shared__ int sh[SCAN_BLK];
    int tid = threadIdx.x;
    int i = blockIdx.x * SCAN_BLK + tid;
    int v = (i < NN) ? g_cnt[i] : 0;
    sh[tid] = v;
    __syncthreads();
#pragma unroll
    for (int s = 1; s < SCAN_BLK; s <<= 1) {
        int t = (tid >= s) ? sh[tid - s] : 0;
        __syncthreads();
        sh[tid] += t;
        __syncthreads();
    }
    if (i < NN) g_off[i] = sh[tid] - v;      // exclusive
    if (tid == SCAN_BLK - 1) g_bsum[blockIdx.x] = sh[tid];
}

__global__ void k_scan2() {
    __shared__ int sh[SCAN_BLK];
    int tid = threadIdx.x;
    int v = (tid < SCAN_NBLK) ? g_bsum[tid] : 0;
    sh[tid] = v;
    __syncthreads();
#pragma unroll
    for (int s = 1; s < SCAN_BLK; s <<= 1) {
        int t = (tid >= s) ? sh[tid - s] : 0;
        __syncthreads();
        sh[tid] += t;
        __syncthreads();
    }
    if (tid < SCAN_NBLK) g_bsum[tid] = sh[tid] - v;   // exclusive block offsets
}

__global__ void k_scan3() {
    int i = blockIdx.x * blockDim.x + threadIdx.x;
    if (i < NN) {
        int o = g_off[i] + g_bsum[i / SCAN_BLK];
        g_off[i] = o;
        g_cursor[i] = o;
    }
    if (i == 0) g_off[NN] = EE;
}

__global__ void k_scatter(const int* __restrict__ ei) {
    int e = blockIdx.x * blockDim.x + threadIdx.x;
    if (e < EE) {
        int c = ei[EE + e];
        int pos = atomicAdd(&g_cursor[c], 1);
        g_perm[pos] = e;
    }
}

// edge embedding (fp16) + norm + row, in dest-sorted order
__global__ void k_edge_enc(const int* __restrict__ ei,
                           const int* __restrict__ attr,
                           const float* __restrict__ bt) {
    int p = blockIdx.x * 8 + (threadIdx.x >> 5);
    if (p >= EE) return;
    int lane = threadIdx.x & 31;
    int e = g_perm[p];
    int r = ei[e], c = ei[EE + e];
    float4 acc = make_float4(0.f, 0.f, 0.f, 0.f);
#pragma unroll
    for (int cc = 0; cc < 3; cc++) {
        int idx = attr[e * 3 + cc];
        const float4* t = (const float4*)(bt + ((size_t)cc * 10 + idx) * DD);
        float4 v = t[lane];
        acc.x += v.x; acc.y += v.y; acc.z += v.z; acc.w += v.w;
    }
    __half2 p0 = __floats2half2_rn(acc.x, acc.y);
    __half2 p1 = __floats2half2_rn(acc.z, acc.w);
    uint2 packed = make_uint2(*(unsigned*)&p0, *(unsigned*)&p1);
    ((uint2*)g_ee16)[(size_t)p * 32 + lane] = packed;
    if (lane == 0) {
        g_rows[p] = r;
        g_norm[p] = g_dis[r] * g_dis[c];
    }
}

// ---------------- GEMM (tf32 mma.sync) with fused BN-in ----------------
// MODE 0: in = g_h (raw).  MODE 1: in = bn_relu(g_agg) (in-place safe), also -> hbuf.
// out: hl16 = fp16(in @ W^T + b)
template <int MODE>
__global__ __launch_bounds__(256, 2)
void k_gemm(const float* __restrict__ Wl, const float* __restrict__ bl,
            float* __restrict__ hbuf) {
    extern __shared__ unsigned smem_u[];
    unsigned* As = smem_u;             // [64][AS]
    unsigned* Bs = smem_u + 64 * AS;   // [128][AS]
    int tid = threadIdx.x;
    int row0 = blockIdx.x * 64;        // NN = 64 * 3125 exactly

    if (blockIdx.x == 0 && tid < DD) { g_sum[tid] = 0.0; g_sq[tid] = 0.0; }

    const float4* src4 = (const float4*)(MODE ? g_agg : g_h) + (size_t)row0 * 32;
    for (int i = tid; i < 64 * 32; i += 256) {
        int r = i >> 5, c4 = i & 31;
        float4 v = __ldcs(&src4[(size_t)r * 32 + c4]);   // streaming: read-once
        if (MODE) {
            float4 sc = ((const float4*)g_scale)[c4];
            float4 sf = ((const float4*)g_shift)[c4];
            v.x = fmaxf(fmaf(v.x, sc.x, sf.x), 0.f);
            v.y = fmaxf(fmaf(v.y, sc.y, sf.y), 0.f);
            v.z = fmaxf(fmaf(v.z, sc.z, sf.z), 0.f);
            v.w = fmaxf(fmaf(v.w, sc.w, sf.w), 0.f);
            __stcs(&((float4*)hbuf)[(size_t)(row0 + r) * 32 + c4], v);  // not read until k_total
        }
        unsigned u0, u1, u2, u3;
        asm("cvt.rna.tf32.f32 %0, %1;" : "=r"(u0) : "f"(v.x));
        asm("cvt.rna.tf32.f32 %0, %1;" : "=r"(u1) : "f"(v.y));
        asm("cvt.rna.tf32.f32 %0, %1;" : "=r"(u2) : "f"(v.z));
        asm("cvt.rna.tf32.f32 %0, %1;" : "=r"(u3) : "f"(v.w));
        *(uint4*)&As[r * AS + c4 * 4] = make_uint4(u0, u1, u2, u3);
    }
    const float4* Wg4 = (const float4*)Wl;
    for (int i = tid; i < 128 * 32; i += 256) {
        int c4 = i & 31;
        float4 v = Wg4[i];
        unsigned u0, u1, u2, u3;
        asm("cvt.rna.tf32.f32 %0, %1;" : "=r"(u0) : "f"(v.x));
        asm("cvt.rna.tf32.f32 %0, %1;" : "=r"(u1) : "f"(v.y));
        asm("cvt.rna.tf32.f32 %0, %1;" : "=r"(u2) : "f"(v.z));
        asm("cvt.rna.tf32.f32 %0, %1;" : "=r"(u3) : "f"(v.w));
        *(uint4*)&Bs[(i >> 5) * AS + c4 * 4] = make_uint4(u0, u1, u2, u3);
    }
    __syncthreads();

    int w = tid >> 5, lane = tid & 31;
    int g = lane >> 2, tig = lane & 3;
    int rbase = (w & 3) * 16;
    int cbase = (w >> 2) * 64;

    float acc[8][4];
#pragma unroll
    for (int j = 0; j < 8; j++)
#pragma unroll
        for (int q = 0; q < 4; q++) acc[j][q] = 0.f;

#pragma unroll
    for (int ks = 0; ks < 16; ks++) {
        int k0 = ks * 8;
        unsigned a0 = As[(rbase + g) * AS + k0 + tig];
        unsigned a1 = As[(rbase + g + 8) * AS + k0 + tig];
        unsigned a2 = As[(rbase + g) * AS + k0 + tig + 4];
        unsigned a3 = As[(rbase + g + 8) * AS + k0 + tig + 4];
#pragma unroll
        for (int j = 0; j < 8; j++) {
            unsigned b0 = Bs[(cbase + j * 8 + g) * AS + k0 + tig];
            unsigned b1 = Bs[(cbase + j * 8 + g) * AS + k0 + tig + 4];
            asm("mma.sync.aligned.m16n8k8.row.col.f32.tf32.tf32.f32 "
                "{%0,%1,%2,%3},{%4,%5,%6,%7},{%8,%9},{%0,%1,%2,%3};"
                : "+f"(acc[j][0]), "+f"(acc[j][1]), "+f"(acc[j][2]), "+f"(acc[j][3])
                : "r"(a0), "r"(a1), "r"(a2), "r"(a3), "r"(b0), "r"(b1));
        }
    }

    int r0g = row0 + rbase + g;
    int r1g = r0g + 8;
#pragma unroll
    for (int j = 0; j < 8; j++) {
        int c0 = cbase + j * 8 + tig * 2;
        float bb0 = bl[c0], bb1 = bl[c0 + 1];
        __half2 h0 = __floats2half2_rn(acc[j][0] + bb0, acc[j][1] + bb1);
        __half2 h1 = __floats2half2_rn(acc[j][2] + bb0, acc[j][3] + bb1);
        *(__half2*)&g_hl16[(size_t)r0g * DD + c0] = h0;   // keep cacheable: reused by gather
        *(__half2*)&g_hl16[(size_t)r1g * DD + c0] = h1;
    }
}

// ---------------- fused: aggregate (CSR by dest, no atomics) + BN stats ----------------
// agg[c] = relu(hl[c]+root)*invdeg + sum_{p in [off[c],off[c+1])} norm[p]*relu(hl[rows[p]]+ee[p])
__global__ void k_msg_fused(const float* __restrict__ rootl) {
    int tid = threadIdx.x;
    int lane = tid & 31;
    int wraw = tid >> 5;
    int gw = blockIdx.x * 8 + wraw;
    const int TOTW = MSG_BLOCKS * 8;
    const int chunk = (NN + TOTW - 1) / TOTW;
    int c0 = gw * chunk;
    int c1 = c0 + chunk; if (c1 > NN) c1 = NN;

    float4 r4 = ((const float4*)rootl)[lane];
    float s0 = 0.f, s1 = 0.f, s2 = 0.f, s3 = 0.f;
    float q0 = 0.f, q1 = 0.f, q2 = 0.f, q3 = 0.f;
    const uint2* hl2 = (const uint2*)g_hl16;   // 32 uint2 per row (reused -> default cache)
    const uint2* ee2 = (const uint2*)g_ee16;   // streamed -> __ldcs
    float4* agg4 = (float4*)g_agg;

    for (int c = c0; c < c1; c++) {
        float idg = g_invdeg[c];
        uint2 hraw = hl2[(size_t)c * 32 + lane];
        float2 f01 = __half22float2(*(__half2*)&hraw.x);
        float2 f23 = __half22float2(*(__half2*)&hraw.y);
        float4 o;
        o.x = fmaxf(f01.x + r4.x, 0.f) * idg;
        o.y = fmaxf(f01.y + r4.y, 0.f) * idg;
        o.z = fmaxf(f23.x + r4.z, 0.f) * idg;
        o.w = fmaxf(f23.y + r4.w, 0.f) * idg;
        int e0 = g_off[c], e1 = g_off[c + 1];
        for (int p = e0; p < e1; p++) {
            int r = __ldcs(&g_rows[p]);
            float nrm = __ldcs(&g_norm[p]);
            uint2 hh = hl2[(size_t)r * 32 + lane];
            uint2 em = __ldcs(&ee2[(size_t)p * 32 + lane]);
            float2 h01 = __half22float2(*(__half2*)&hh.x);
            float2 h23 = __half22float2(*(__half2*)&hh.y);
            float2 e01 = __half22float2(*(__half2*)&em.x);
            float2 e23 = __half22float2(*(__half2*)&em.y);
            o.x = fmaf(nrm, fmaxf(h01.x + e01.x, 0.f), o.x);
            o.y = fmaf(nrm, fmaxf(h01.y + e01.y, 0.f), o.y);
            o.z = fmaf(nrm, fmaxf(h23.x + e23.x, 0.f), o.z);
            o.w = fmaf(nrm, fmaxf(h23.y + e23.y, 0.f), o.w);
        }
        __stcs(&agg4[(size_t)c * 32 + lane], o);   // streamed out; re-read next layer only
        s0 += o.x; s1 += o.y; s2 += o.z; s3 += o.w;
        q0 += o.x * o.x; q1 += o.y * o.y; q2 += o.z * o.z; q3 += o.w * o.w;
    }

    __shared__ float sh[256][4];
    sh[tid][0] = s0; sh[tid][1] = s1; sh[tid][2] = s2; sh[tid][3] = s3;
    __syncthreads();
    if (wraw == 0) {
        float t0 = 0.f, t1 = 0.f, t2 = 0.f, t3 = 0.f;
#pragma unroll
        for (int g = 0; g < 8; g++) {
            t0 += sh[g * 32 + lane][0];
            t1 += sh[g * 32 + lane][1];
            t2 += sh[g * 32 + lane][2];
            t3 += sh[g * 32 + lane][3];
        }
        atomicAdd(&g_sum[lane * 4 + 0], (double)t0);
        atomicAdd(&g_sum[lane * 4 + 1], (double)t1);
        atomicAdd(&g_sum[lane * 4 + 2], (double)t2);
        atomicAdd(&g_sum[lane * 4 + 3], (double)t3);
    }
    __syncthreads();
    sh[tid][0] = q0; sh[tid][1] = q1; sh[tid][2] = q2; sh[tid][3] = q3;
    __syncthreads();
    if (wraw == 0) {
        float t0 = 0.f, t1 = 0.f, t2 = 0.f, t3 = 0.f;
#pragma unroll
        for (int g = 0; g < 8; g++) {
            t0 += sh[g * 32 + lane][0];
            t1 += sh[g * 32 + lane][1];
            t2 += sh[g * 32 + lane][2];
            t3 += sh[g * 32 + lane][3];
        }
        atomicAdd(&g_sq[lane * 4 + 0], (double)t0);
        atomicAdd(&g_sq[lane * 4 + 1], (double)t1);
        atomicAdd(&g_sq[lane * 4 + 2], (double)t2);
        atomicAdd(&g_sq[lane * 4 + 3], (double)t3);
    }
}

__global__ void k_bn_prep(const float* __restrict__ gammal,
                          const float* __restrict__ betal) {
    int c = threadIdx.x;
    double mean = g_sum[c] / (double)NN;
    double var = g_sq[c] / (double)NN - mean * mean;
    if (var < 0.0) var = 0.0;
    float inv = rsqrtf((float)var + BN_EPS);
    float sc = gammal[c] * inv;
    g_scale[c] = sc;
    g_shift[c] = betal[c] - (float)mean * sc;
}

// final: out += h1..h4 + bn(agg_last) (no relu)
__global__ void k_total(float* __restrict__ out) {
    size_t idx = (size_t)blockIdx.x * blockDim.x + threadIdx.x;  // NN*32 float4s
    int lane = idx & 31;
    float4 a = __ldcs(&((const float4*)g_agg)[idx]);
    float4 sc = ((const float4*)g_scale)[lane];
    float4 sf = ((const float4*)g_shift)[lane];
    float4 t = __ldcs(&((const float4*)out)[idx]);
    t.x += fmaf(a.x, sc.x, sf.x);
    t.y += fmaf(a.y, sc.y, sf.y);
    t.z += fmaf(a.z, sc.z, sf.z);
    t.w += fmaf(a.w, sc.w, sf.w);
    const float4* hb = (const float4*)g_hbuf;
    size_t stride = (size_t)NN * 32;
#pragma unroll
    for (int l = 0; l < 4; l++) {
        float4 v = __ldcs(&hb[idx + stride * l]);
        t.x += v.x; t.y += v.y; t.z += v.z; t.w += v.w;
    }
    __stcs(&((float4*)out)[idx], t);
}

// ---------------- launch ----------------
extern "C" void kernel_launch(void* const* d_in, const int* in_sizes, int n_in,
                              void* d_out, int out_size) {
    const int*   x     = (const int*)d_in[0];
    const int*   ei    = (const int*)d_in[1];
    const int*   attr  = (const int*)d_in[2];
    const float* at    = (const float*)d_in[3];
    const float* bt    = (const float*)d_in[4];
    const float* W     = (const float*)d_in[5];
    const float* b     = (const float*)d_in[6];
    const float* root  = (const float*)d_in[7];
    const float* gamma = (const float*)d_in[8];
    const float* beta  = (const float*)d_in[9];
    float* out = (float*)d_out;

    cudaFuncSetAttribute(k_gemm<0>, cudaFuncAttributeMaxDynamicSharedMemorySize, GEMM_SMEM);
    cudaFuncSetAttribute(k_gemm<1>, cudaFuncAttributeMaxDynamicSharedMemorySize, GEMM_SMEM);

    k_node_enc<<<NN / 8, 256>>>(x, at, out);
    k_deg_init<<<(NN + 255) / 256, 256>>>();
    k_deg_count<<<(EE + 255) / 256, 256>>>(ei);
    k_dis<<<(NN + 255) / 256, 256>>>();
    k_scan1<<<SCAN_NBLK, SCAN_BLK>>>();
    k_scan2<<<1, SCAN_BLK>>>();
    k_scan3<<<(NN + 255) / 256, 256>>>();
    k_scatter<<<(EE + 255) / 256, 256>>>(ei);
    k_edge_enc<<<EE / 8, 256>>>(ei, attr, bt);

    float* hbuf = (float*)nullptr;
    cudaGetSymbolAddress((void**)&hbuf, g_hbuf);
    for (int l = 0; l < LL; l++) {
        const float* Wl = W + (size_t)l * DD * DD;
        const float* bl = b + (size_t)l * DD;
        if (l == 0) {
            k_gemm<0><<<NN / 64, 256, GEMM_SMEM>>>(Wl, bl, nullptr);
        } else {
            k_gemm<1><<<NN / 64, 256, GEMM_SMEM>>>(Wl, bl,
                                                   hbuf + (size_t)(l - 1) * NN * DD);
        }
        k_msg_fused<<<MSG_BLOCKS, 256>>>(root + (size_t)l * DD);
        k_bn_prep<<<1, 128>>>(gamma + (size_t)l * DD, beta + (size_t)l * DD);
    }
    k_total<<<NN * 32 / 256, 256>>>(out);
}

// round 9
// speedup vs baseline: 1.1893x; 1.1893x over previous
#include <cuda_runtime.h>
#include <cuda_fp16.h>

#define NN 200000
#define EE 400000
#define DD 128
#define LL 5
#define BN_EPS 1e-5f

#define AS2 68                          // padded smem stride (u32 = 2 halfs each); 64 data + 4 pad
#define GEMM_SMEM ((64 * AS2 + 128 * AS2) * 4)
#define MSG_BLOCKS 1184
#define SCAN_BLK 512
#define SCAN_NBLK ((NN + SCAN_BLK - 1) / SCAN_BLK)   // 391

// ---------------- scratch (static device globals; no allocation) ----------------
__device__ float  g_h[(size_t)NN * DD];       // h0 (layer-0 input)
__device__ __half g_hl16[(size_t)NN * DD];    // linear output (fp16)
__device__ float  g_agg[(size_t)NN * DD];     // pre-BN layer output
__device__ float  g_hbuf[(size_t)4 * NN * DD]; // post-BN h1..h4 for final total
__device__ __half g_ee16[(size_t)EE * DD];    // edge embeddings (dest-sorted, fp16)
__device__ float  g_norm[EE];                 // dest-sorted
__device__ int    g_rows[EE];                 // dest-sorted src
__device__ int    g_perm[EE];
__device__ int    g_cnt[NN];
__device__ int    g_off[NN + 1];
__device__ int    g_cursor[NN];
__device__ int    g_bsum[SCAN_BLK];
__device__ float  g_deg[NN];
__device__ float  g_dis[NN];
__device__ float  g_invdeg[NN];
__device__ double g_sum[DD];
__device__ double g_sq[DD];
__device__ float  g_scale[DD];
__device__ float  g_shift[DD];

// ---------------- encoders / setup ----------------
__global__ void k_node_enc(const int* __restrict__ x,
                           const float* __restrict__ at,
                           float* __restrict__ out) {
    int node = blockIdx.x * 8 + (threadIdx.x >> 5);
    if (node >= NN) return;
    int lane = threadIdx.x & 31;
    float4 acc = make_float4(0.f, 0.f, 0.f, 0.f);
#pragma unroll
    for (int c = 0; c < 9; c++) {
        int idx = x[node * 9 + c];
        const float4* t = (const float4*)(at + ((size_t)c * 100 + idx) * DD);
        float4 v = t[lane];
        acc.x += v.x; acc.y += v.y; acc.z += v.z; acc.w += v.w;
    }
    size_t o = (size_t)node * 32 + lane;
    ((float4*)g_h)[o] = acc;
    ((float4*)out)[o] = acc;
}

__global__ void k_deg_init() {
    int i = blockIdx.x * blockDim.x + threadIdx.x;
    if (i < NN) { g_deg[i] = 1.0f; g_cnt[i] = 0; }
}

__global__ void k_deg_count(const int* __restrict__ ei) {
    int e = blockIdx.x * blockDim.x + threadIdx.x;
    if (e < EE) {
        atomicAdd(&g_deg[ei[e]], 1.0f);        // by source (degree)
        atomicAdd(&g_cnt[ei[EE + e]], 1);      // by dest (sort histogram)
    }
}

__global__ void k_dis() {
    int i = blockIdx.x * blockDim.x + threadIdx.x;
    if (i < NN) {
        float d = g_deg[i];
        g_dis[i] = rsqrtf(d);
        g_invdeg[i] = 1.0f / d;
    }
}

// ---- 2-level exclusive scan of g_cnt -> g_off ----
__global__ void k_scan1() {
    __shared__ int sh[SCAN_BLK];
    int tid = threadIdx.x;
    int i = blockIdx.x * SCAN_BLK + tid;
    int v = (i < NN) ? g_cnt[i] : 0;
    sh[tid] = v;
    __syncthreads();
#pragma unroll
    for (int s = 1; s < SCAN_BLK; s <<= 1) {
        int t = (tid >= s) ? sh[tid - s] : 0;
        __syncthreads();
        sh[tid] += t;
        __syncthreads();
    }
    if (i < NN) g_off[i] = sh[tid] - v;      // exclusive
    if (tid == SCAN_BLK - 1) g_bsum[blockIdx.x] = sh[tid];
}

__global__ void k_scan2() {
    __shared__ int sh[SCAN_BLK];
    int tid = threadIdx.x;
    int v = (tid < SCAN_NBLK) ? g_bsum[tid] : 0;
    sh[tid] = v;
    __syncthreads();
#pragma unroll
    for (int s = 1; s < SCAN_BLK; s <<= 1) {
        int t = (tid >= s) ? sh[tid - s] : 0;
        __syncthreads();
        sh[tid] += t;
        __syncthreads();
    }
    if (tid < SCAN_NBLK) g_bsum[tid] = sh[tid] - v;   // exclusive block offsets
}

__global__ void k_scan3() {
    int i = blockIdx.x * blockDim.x + threadIdx.x;
    if (i < NN) {
        int o = g_off[i] + g_bsum[i / SCAN_BLK];
        g_off[i] = o;
        g_cursor[i] = o;
    }
    if (i == 0) g_off[NN] = EE;
}

__global__ void k_scatter(const int* __restrict__ ei) {
    int e = blockIdx.x * blockDim.x + threadIdx.x;
    if (e < EE) {
        int c = ei[EE + e];
        int pos = atomicAdd(&g_cursor[c], 1);
        g_perm[pos] = e;
    }
}

// edge embedding (fp16) + norm + row, in dest-sorted order
__global__ void k_edge_enc(const int* __restrict__ ei,
                           const int* __restrict__ attr,
                           const float* __restrict__ bt) {
    int p = blockIdx.x * 8 + (threadIdx.x >> 5);
    if (p >= EE) return;
    int lane = threadIdx.x & 31;
    int e = g_perm[p];
    int r = ei[e], c = ei[EE + e];
    float4 acc = make_float4(0.f, 0.f, 0.f, 0.f);
#pragma unroll
    for (int cc = 0; cc < 3; cc++) {
        int idx = attr[e * 3 + cc];
        const float4* t = (const float4*)(bt + ((size_t)cc * 10 + idx) * DD);
        float4 v = t[lane];
        acc.x += v.x; acc.y += v.y; acc.z += v.z; acc.w += v.w;
    }
    __half2 p0 = __floats2half2_rn(acc.x, acc.y);
    __half2 p1 = __floats2half2_rn(acc.z, acc.w);
    uint2 packed = make_uint2(*(unsigned*)&p0, *(unsigned*)&p1);
    ((uint2*)g_ee16)[(size_t)p * 32 + lane] = packed;
    if (lane == 0) {
        g_rows[p] = r;
        g_norm[p] = g_dis[r] * g_dis[c];
    }
}

// ---------------- GEMM (fp16 mma.sync m16n8k16, fp32 accum) with fused BN-in ----------------
// MODE 0: in = g_h (raw).  MODE 1: in = bn_relu(g_agg) (in-place safe), also -> hbuf.
// out: hl16 = fp16(in @ W^T + b)
template <int MODE>
__global__ __launch_bounds__(256, 3)
void k_gemm(const float* __restrict__ Wl, const float* __restrict__ bl,
            float* __restrict__ hbuf) {
    extern __shared__ unsigned smem_u[];
    unsigned* As = smem_u;              // [64][AS2] u32 = 2 halfs (k-major)
    unsigned* Bs = smem_u + 64 * AS2;   // [128][AS2]
    int tid = threadIdx.x;
    int row0 = blockIdx.x * 64;         // NN = 64 * 3125 exactly

    if (blockIdx.x == 0 && tid < DD) { g_sum[tid] = 0.0; g_sq[tid] = 0.0; }

    // stage A rows (apply BN+relu for MODE 1), fp32 -> fp16 pairs
    const float4* src4 = (const float4*)(MODE ? g_agg : g_h) + (size_t)row0 * 32;
    for (int i = tid; i < 64 * 32; i += 256) {
        int r = i >> 5, c4 = i & 31;
        float4 v = src4[(size_t)r * 32 + c4];
        if (MODE) {
            float4 sc = ((const float4*)g_scale)[c4];
            float4 sf = ((const float4*)g_shift)[c4];
            v.x = fmaxf(fmaf(v.x, sc.x, sf.x), 0.f);
            v.y = fmaxf(fmaf(v.y, sc.y, sf.y), 0.f);
            v.z = fmaxf(fmaf(v.z, sc.z, sf.z), 0.f);
            v.w = fmaxf(fmaf(v.w, sc.w, sf.w), 0.f);
            ((float4*)hbuf)[(size_t)(row0 + r) * 32 + c4] = v;
        }
        __half2 h01 = __floats2half2_rn(v.x, v.y);
        __half2 h23 = __floats2half2_rn(v.z, v.w);
        *(uint2*)&As[r * AS2 + c4 * 2] = make_uint2(*(unsigned*)&h01, *(unsigned*)&h23);
    }
    const float4* Wg4 = (const float4*)Wl;
    for (int i = tid; i < 128 * 32; i += 256) {
        int n = i >> 5, c4 = i & 31;
        float4 v = Wg4[i];
        __half2 h01 = __floats2half2_rn(v.x, v.y);
        __half2 h23 = __floats2half2_rn(v.z, v.w);
        *(uint2*)&Bs[n * AS2 + c4 * 2] = make_uint2(*(unsigned*)&h01, *(unsigned*)&h23);
    }
    __syncthreads();

    int w = tid >> 5, lane = tid & 31;
    int g = lane >> 2, tig = lane & 3;
    int rbase = (w & 3) * 16;           // warp row tile within 64
    int cbase = (w >> 2) * 64;          // warp col tile within 128

    float acc[8][4];
#pragma unroll
    for (int j = 0; j < 8; j++)
#pragma unroll
        for (int q = 0; q < 4; q++) acc[j][q] = 0.f;

#pragma unroll
    for (int ks = 0; ks < 8; ks++) {    // K=128, 16 per mma
        int k2 = ks * 8;                // u32 offset (8 u32 = 16 halfs)
        unsigned a0 = As[(rbase + g) * AS2 + k2 + tig];
        unsigned a1 = As[(rbase + g + 8) * AS2 + k2 + tig];
        unsigned a2 = As[(rbase + g) * AS2 + k2 + tig + 4];
        unsigned a3 = As[(rbase + g + 8) * AS2 + k2 + tig + 4];
#pragma unroll
        for (int j = 0; j < 8; j++) {
            unsigned b0 = Bs[(cbase + j * 8 + g) * AS2 + k2 + tig];
            unsigned b1 = Bs[(cbase + j * 8 + g) * AS2 + k2 + tig + 4];
            asm("mma.sync.aligned.m16n8k16.row.col.f32.f16.f16.f32 "
                "{%0,%1,%2,%3},{%4,%5,%6,%7},{%8,%9},{%0,%1,%2,%3};"
                : "+f"(acc[j][0]), "+f"(acc[j][1]), "+f"(acc[j][2]), "+f"(acc[j][3])
                : "r"(a0), "r"(a1), "r"(a2), "r"(a3), "r"(b0), "r"(b1));
        }
    }

    int r0g = row0 + rbase + g;
    int r1g = r0g + 8;
#pragma unroll
    for (int j = 0; j < 8; j++) {
        int c0 = cbase + j * 8 + tig * 2;
        float bb0 = bl[c0], bb1 = bl[c0 + 1];
        __half2 h0 = __floats2half2_rn(acc[j][0] + bb0, acc[j][1] + bb1);
        __half2 h1 = __floats2half2_rn(acc[j][2] + bb0, acc[j][3] + bb1);
        *(__half2*)&g_hl16[(size_t)r0g * DD + c0] = h0;
        *(__half2*)&g_hl16[(size_t)r1g * DD + c0] = h1;
    }
}

// ---------------- fused: aggregate (CSR by dest, no atomics) + BN stats ----------------
// agg[c] = relu(hl[c]+root)*invdeg + sum_{p in [off[c],off[c+1])} norm[p]*relu(hl[rows[p]]+ee[p])
__global__ void k_msg_fused(const float* __restrict__ rootl) {
    int tid = threadIdx.x;
    int lane = tid & 31;
    int wraw = tid >> 5;
    int gw = blockIdx.x * 8 + wraw;
    const int TOTW = MSG_BLOCKS * 8;
    const int chunk = (NN + TOTW - 1) / TOTW;
    int c0 = gw * chunk;
    int c1 = c0 + chunk; if (c1 > NN) c1 = NN;

    float4 r4 = ((const float4*)rootl)[lane];
    float s0 = 0.f, s1 = 0.f, s2 = 0.f, s3 = 0.f;
    float q0 = 0.f, q1 = 0.f, q2 = 0.f, q3 = 0.f;
    const uint2* hl2 = (const uint2*)g_hl16;
    const uint2* ee2 = (const uint2*)g_ee16;
    float4* agg4 = (float4*)g_agg;

    for (int c = c0; c < c1; c++) {
        float idg = g_invdeg[c];
        uint2 hraw = hl2[(size_t)c * 32 + lane];
        float2 f01 = __half22float2(*(__half2*)&hraw.x);
        float2 f23 = __half22float2(*(__half2*)&hraw.y);
        float4 o;
        o.x = fmaxf(f01.x + r4.x, 0.f) * idg;
        o.y = fmaxf(f01.y + r4.y, 0.f) * idg;
        o.z = fmaxf(f23.x + r4.z, 0.f) * idg;
        o.w = fmaxf(f23.y + r4.w, 0.f) * idg;
        int e0 = g_off[c], e1 = g_off[c + 1];
        for (int p = e0; p < e1; p++) {
            int r = g_rows[p];
            float nrm = g_norm[p];
            uint2 hh = hl2[(size_t)r * 32 + lane];
            uint2 em = ee2[(size_t)p * 32 + lane];
            float2 h01 = __half22float2(*(__half2*)&hh.x);
            float2 h23 = __half22float2(*(__half2*)&hh.y);
            float2 e01 = __half22float2(*(__half2*)&em.x);
            float2 e23 = __half22float2(*(__half2*)&em.y);
            o.x = fmaf(nrm, fmaxf(h01.x + e01.x, 0.f), o.x);
            o.y = fmaf(nrm, fmaxf(h01.y + e01.y, 0.f), o.y);
            o.z = fmaf(nrm, fmaxf(h23.x + e23.x, 0.f), o.z);
            o.w = fmaf(nrm, fmaxf(h23.y + e23.y, 0.f), o.w);
        }
        agg4[(size_t)c * 32 + lane] = o;
        s0 += o.x; s1 += o.y; s2 += o.z; s3 += o.w;
        q0 += o.x * o.x; q1 += o.y * o.y; q2 += o.z * o.z; q3 += o.w * o.w;
    }

    __shared__ float sh[256][4];
    sh[tid][0] = s0; sh[tid][1] = s1; sh[tid][2] = s2; sh[tid][3] = s3;
    __syncthreads();
    if (wraw == 0) {
        float t0 = 0.f, t1 = 0.f, t2 = 0.f, t3 = 0.f;
#pragma unroll
        for (int g = 0; g < 8; g++) {
            t0 += sh[g * 32 + lane][0];
            t1 += sh[g * 32 + lane][1];
            t2 += sh[g * 32 + lane][2];
            t3 += sh[g * 32 + lane][3];
        }
        atomicAdd(&g_sum[lane * 4 + 0], (double)t0);
        atomicAdd(&g_sum[lane * 4 + 1], (double)t1);
        atomicAdd(&g_sum[lane * 4 + 2], (double)t2);
        atomicAdd(&g_sum[lane * 4 + 3], (double)t3);
    }
    __syncthreads();
    sh[tid][0] = q0; sh[tid][1] = q1; sh[tid][2] = q2; sh[tid][3] = q3;
    __syncthreads();
    if (wraw == 0) {
        float t0 = 0.f, t1 = 0.f, t2 = 0.f, t3 = 0.f;
#pragma unroll
        for (int g = 0; g < 8; g++) {
            t0 += sh[g * 32 + lane][0];
            t1 += sh[g * 32 + lane][1];
            t2 += sh[g * 32 + lane][2];
            t3 += sh[g * 32 + lane][3];
        }
        atomicAdd(&g_sq[lane * 4 + 0], (double)t0);
        atomicAdd(&g_sq[lane * 4 + 1], (double)t1);
        atomicAdd(&g_sq[lane * 4 + 2], (double)t2);
        atomicAdd(&g_sq[lane * 4 + 3], (double)t3);
    }
}

__global__ void k_bn_prep(const float* __restrict__ gammal,
                          const float* __restrict__ betal) {
    int c = threadIdx.x;
    double mean = g_sum[c] / (double)NN;
    double var = g_sq[c] / (double)NN - mean * mean;
    if (var < 0.0) var = 0.0;
    float inv = rsqrtf((float)var + BN_EPS);
    float sc = gammal[c] * inv;
    g_scale[c] = sc;
    g_shift[c] = betal[c] - (float)mean * sc;
}

// final: out += h1..h4 + bn(agg_last) (no relu)
__global__ void k_total(float* __restrict__ out) {
    size_t idx = (size_t)blockIdx.x * blockDim.x + threadIdx.x;  // NN*32 float4s
    int lane = idx & 31;
    float4 a = ((const float4*)g_agg)[idx];
    float4 sc = ((const float4*)g_scale)[lane];
    float4 sf = ((const float4*)g_shift)[lane];
    float4 t = ((const float4*)out)[idx];
    t.x += fmaf(a.x, sc.x, sf.x);
    t.y += fmaf(a.y, sc.y, sf.y);
    t.z += fmaf(a.z, sc.z, sf.z);
    t.w += fmaf(a.w, sc.w, sf.w);
    const float4* hb = (const float4*)g_hbuf;
    size_t stride = (size_t)NN * 32;
#pragma unroll
    for (int l = 0; l < 4; l++) {
        float4 v = hb[idx + stride * l];
        t.x += v.x; t.y += v.y; t.z += v.z; t.w += v.w;
    }
    ((float4*)out)[idx] = t;
}

// ---------------- launch ----------------
extern "C" void kernel_launch(void* const* d_in, const int* in_sizes, int n_in,
                              void* d_out, int out_size) {
    const int*   x     = (const int*)d_in[0];
    const int*   ei    = (const int*)d_in[1];
    const int*   attr  = (const int*)d_in[2];
    const float* at    = (const float*)d_in[3];
    const float* bt    = (const float*)d_in[4];
    const float* W     = (const float*)d_in[5];
    const float* b     = (const float*)d_in[6];
    const float* root  = (const float*)d_in[7];
    const float* gamma = (const float*)d_in[8];
    const float* beta  = (const float*)d_in[9];
    float* out = (float*)d_out;

    cudaFuncSetAttribute(k_gemm<0>, cudaFuncAttributeMaxDynamicSharedMemorySize, GEMM_SMEM);
    cudaFuncSetAttribute(k_gemm<1>, cudaFuncAttributeMaxDynamicSharedMemorySize, GEMM_SMEM);

    k_node_enc<<<NN / 8, 256>>>(x, at, out);
    k_deg_init<<<(NN + 255) / 256, 256>>>();
    k_deg_count<<<(EE + 255) / 256, 256>>>(ei);
    k_dis<<<(NN + 255) / 256, 256>>>();
    k_scan1<<<SCAN_NBLK, SCAN_BLK>>>();
    k_scan2<<<1, SCAN_BLK>>>();
    k_scan3<<<(NN + 255) / 256, 256>>>();
    k_scatter<<<(EE + 255) / 256, 256>>>(ei);
    k_edge_enc<<<EE / 8, 256>>>(ei, attr, bt);

    float* hbuf = (float*)nullptr;
    cudaGetSymbolAddress((void**)&hbuf, g_hbuf);
    for (int l = 0; l < LL; l++) {
        const float* Wl = W + (size_t)l * DD * DD;
        const float* bl = b + (size_t)l * DD;
        if (l == 0) {
            k_gemm<0><<<NN / 64, 256, GEMM_SMEM>>>(Wl, bl, nullptr);
        } else {
            k_gemm<1><<<NN / 64, 256, GEMM_SMEM>>>(Wl, bl,
                                                   hbuf + (size_t)(l - 1) * NN * DD);
        }
        k_msg_fused<<<MSG_BLOCKS, 256>>>(root + (size_t)l * DD);
        k_bn_prep<<<1, 128>>>(gamma + (size_t)l * DD, beta + (size_t)l * DD);
    }
    k_total<<<NN * 32 / 256, 256>>>(out);
}

// round 10
// speedup vs baseline: 1.2898x; 1.0846x over previous
#include <cuda_runtime.h>
#include <cuda_fp16.h>

#define NN 200000
#define EE 400000
#define DD 128
#define LL 5
#define BN_EPS 1e-5f

#define AS2 68                          // padded smem stride (u32 = 2 halfs each); 64 data + 4 pad
#define GEMM_SMEM ((64 * AS2 + 128 * AS2) * 4)
#define MSG_BLOCKS 1184
#define SCAN_BLK 512
#define SCAN_NBLK ((NN + SCAN_BLK - 1) / SCAN_BLK)   // 391

// ---------------- scratch (static device globals; no allocation) ----------------
__device__ float  g_h[(size_t)NN * DD];        // h0 (layer-0 input)
__device__ __half g_hl16[(size_t)NN * DD];     // linear output (fp16)
__device__ __half g_agg16[(size_t)NN * DD];    // pre-BN layer output (fp16)
__device__ __half g_hbuf16[(size_t)4 * NN * DD]; // post-BN h1..h4 (fp16) for final total
__device__ __half g_ee16[(size_t)EE * DD];     // edge embeddings (dest-sorted, fp16)
__device__ float  g_norm[EE];                  // dest-sorted
__device__ int    g_rows[EE];                  // dest-sorted src
__device__ int    g_perm[EE];
__device__ int    g_cnt[NN];
__device__ int    g_off[NN + 1];
__device__ int    g_cursor[NN];
__device__ int    g_bsum[SCAN_BLK];
__device__ float  g_deg[NN];
__device__ float  g_dis[NN];
__device__ float  g_invdeg[NN];
__device__ double g_sum[DD];
__device__ double g_sq[DD];
__device__ float  g_scale[DD];
__device__ float  g_shift[DD];

// ---------------- encoders / setup ----------------
__global__ void k_node_enc(const int* __restrict__ x,
                           const float* __restrict__ at,
                           float* __restrict__ out) {
    int node = blockIdx.x * 8 + (threadIdx.x >> 5);
    if (node >= NN) return;
    int lane = threadIdx.x & 31;
    float4 acc = make_float4(0.f, 0.f, 0.f, 0.f);
#pragma unroll
    for (int c = 0; c < 9; c++) {
        int idx = x[node * 9 + c];
        const float4* t = (const float4*)(at + ((size_t)c * 100 + idx) * DD);
        float4 v = t[lane];
        acc.x += v.x; acc.y += v.y; acc.z += v.z; acc.w += v.w;
    }
    size_t o = (size_t)node * 32 + lane;
    ((float4*)g_h)[o] = acc;
    ((float4*)out)[o] = acc;
}

__global__ void k_deg_init() {
    int i = blockIdx.x * blockDim.x + threadIdx.x;
    if (i < NN) { g_deg[i] = 1.0f; g_cnt[i] = 0; }
}

__global__ void k_deg_count(const int* __restrict__ ei) {
    int e = blockIdx.x * blockDim.x + threadIdx.x;
    if (e < EE) {
        atomicAdd(&g_deg[ei[e]], 1.0f);        // by source (degree)
        atomicAdd(&g_cnt[ei[EE + e]], 1);      // by dest (sort histogram)
    }
}

__global__ void k_dis() {
    int i = blockIdx.x * blockDim.x + threadIdx.x;
    if (i < NN) {
        float d = g_deg[i];
        g_dis[i] = rsqrtf(d);
        g_invdeg[i] = 1.0f / d;
    }
}

// ---- 2-level exclusive scan of g_cnt -> g_off ----
__global__ void k_scan1() {
    __shared__ int sh[SCAN_BLK];
    int tid = threadIdx.x;
    int i = blockIdx.x * SCAN_BLK + tid;
    int v = (i < NN) ? g_cnt[i] : 0;
    sh[tid] = v;
    __syncthreads();
#pragma unroll
    for (int s = 1; s < SCAN_BLK; s <<= 1) {
        int t = (tid >= s) ? sh[tid - s] : 0;
        __syncthreads();
        sh[tid] += t;
        __syncthreads();
    }
    if (i < NN) g_off[i] = sh[tid] - v;      // exclusive
    if (tid == SCAN_BLK - 1) g_bsum[blockIdx.x] = sh[tid];
}

__global__ void k_scan2() {
    __shared__ int sh[SCAN_BLK];
    int tid = threadIdx.x;
    int v = (tid < SCAN_NBLK) ? g_bsum[tid] : 0;
    sh[tid] = v;
    __syncthreads();
#pragma unroll
    for (int s = 1; s < SCAN_BLK; s <<= 1) {
        int t = (tid >= s) ? sh[tid - s] : 0;
        __syncthreads();
        sh[tid] += t;
        __syncthreads();
    }
    if (tid < SCAN_NBLK) g_bsum[tid] = sh[tid] - v;   // exclusive block offsets
}

__global__ void k_scan3() {
    int i = blockIdx.x * blockDim.x + threadIdx.x;
    if (i < NN) {
        int o = g_off[i] + g_bsum[i / SCAN_BLK];
        g_off[i] = o;
        g_cursor[i] = o;
    }
    if (i == 0) g_off[NN] = EE;
}

__global__ void k_scatter(const int* __restrict__ ei) {
    int e = blockIdx.x * blockDim.x + threadIdx.x;
    if (e < EE) {
        int c = ei[EE + e];
        int pos = atomicAdd(&g_cursor[c], 1);
        g_perm[pos] = e;
    }
}

// edge embedding (fp16) + norm + row, in dest-sorted order
__global__ void k_edge_enc(const int* __restrict__ ei,
                           const int* __restrict__ attr,
                           const float* __restrict__ bt) {
    int p = blockIdx.x * 8 + (threadIdx.x >> 5);
    if (p >= EE) return;
    int lane = threadIdx.x & 31;
    int e = g_perm[p];
    int r = ei[e], c = ei[EE + e];
    float4 acc = make_float4(0.f, 0.f, 0.f, 0.f);
#pragma unroll
    for (int cc = 0; cc < 3; cc++) {
        int idx = attr[e * 3 + cc];
        const float4* t = (const float4*)(bt + ((size_t)cc * 10 + idx) * DD);
        float4 v = t[lane];
        acc.x += v.x; acc.y += v.y; acc.z += v.z; acc.w += v.w;
    }
    __half2 p0 = __floats2half2_rn(acc.x, acc.y);
    __half2 p1 = __floats2half2_rn(acc.z, acc.w);
    uint2 packed = make_uint2(*(unsigned*)&p0, *(unsigned*)&p1);
    ((uint2*)g_ee16)[(size_t)p * 32 + lane] = packed;
    if (lane == 0) {
        g_rows[p] = r;
        g_norm[p] = g_dis[r] * g_dis[c];
    }
}

// ---------------- GEMM (fp16 mma.sync m16n8k16, fp32 accum) with fused BN-in ----------------
// MODE 0: in = g_h (fp32 raw).  MODE 1: in = bn_relu(g_agg16), post-BN fp16 also -> hbuf16.
// out: hl16 = fp16(in @ W^T + b)
template <int MODE>
__global__ __launch_bounds__(256, 3)
void k_gemm(const float* __restrict__ Wl, const float* __restrict__ bl,
            __half* __restrict__ hbuf) {
    extern __shared__ unsigned smem_u[];
    unsigned* As = smem_u;              // [64][AS2] u32 = 2 halfs (k-major)
    unsigned* Bs = smem_u + 64 * AS2;   // [128][AS2]
    int tid = threadIdx.x;
    int row0 = blockIdx.x * 64;         // NN = 64 * 3125 exactly

    if (blockIdx.x == 0 && tid < DD) { g_sum[tid] = 0.0; g_sq[tid] = 0.0; }

    if (MODE) {
        // stage A rows from fp16 agg, apply BN+relu, emit fp16 to smem + hbuf
        const uint2* src2 = (const uint2*)g_agg16 + (size_t)row0 * 32;
        for (int i = tid; i < 64 * 32; i += 256) {
            int r = i >> 5, c4 = i & 31;
            uint2 a = src2[(size_t)r * 32 + c4];
            float2 f01 = __half22float2(*(__half2*)&a.x);
            float2 f23 = __half22float2(*(__half2*)&a.y);
            float4 sc = ((const float4*)g_scale)[c4];
            float4 sf = ((const float4*)g_shift)[c4];
            float vx = fmaxf(fmaf(f01.x, sc.x, sf.x), 0.f);
            float vy = fmaxf(fmaf(f01.y, sc.y, sf.y), 0.f);
            float vz = fmaxf(fmaf(f23.x, sc.z, sf.z), 0.f);
            float vw = fmaxf(fmaf(f23.y, sc.w, sf.w), 0.f);
            __half2 h01 = __floats2half2_rn(vx, vy);
            __half2 h23 = __floats2half2_rn(vz, vw);
            uint2 packed = make_uint2(*(unsigned*)&h01, *(unsigned*)&h23);
            ((uint2*)hbuf)[(size_t)(row0 + r) * 32 + c4] = packed;
            *(uint2*)&As[r * AS2 + c4 * 2] = packed;
        }
    } else {
        const float4* src4 = (const float4*)g_h + (size_t)row0 * 32;
        for (int i = tid; i < 64 * 32; i += 256) {
            int r = i >> 5, c4 = i & 31;
            float4 v = src4[(size_t)r * 32 + c4];
            __half2 h01 = __floats2half2_rn(v.x, v.y);
            __half2 h23 = __floats2half2_rn(v.z, v.w);
            *(uint2*)&As[r * AS2 + c4 * 2] = make_uint2(*(unsigned*)&h01, *(unsigned*)&h23);
        }
    }
    const float4* Wg4 = (const float4*)Wl;
    for (int i = tid; i < 128 * 32; i += 256) {
        int n = i >> 5, c4 = i & 31;
        float4 v = Wg4[i];
        __half2 h01 = __floats2half2_rn(v.x, v.y);
        __half2 h23 = __floats2half2_rn(v.z, v.w);
        *(uint2*)&Bs[n * AS2 + c4 * 2] = make_uint2(*(unsigned*)&h01, *(unsigned*)&h23);
    }
    __syncthreads();

    int w = tid >> 5, lane = tid & 31;
    int g = lane >> 2, tig = lane & 3;
    int rbase = (w & 3) * 16;           // warp row tile within 64
    int cbase = (w >> 2) * 64;          // warp col tile within 128

    float acc[8][4];
#pragma unroll
    for (int j = 0; j < 8; j++)
#pragma unroll
        for (int q = 0; q < 4; q++) acc[j][q] = 0.f;

#pragma unroll
    for (int ks = 0; ks < 8; ks++) {    // K=128, 16 per mma
        int k2 = ks * 8;                // u32 offset (8 u32 = 16 halfs)
        unsigned a0 = As[(rbase + g) * AS2 + k2 + tig];
        unsigned a1 = As[(rbase + g + 8) * AS2 + k2 + tig];
        unsigned a2 = As[(rbase + g) * AS2 + k2 + tig + 4];
        unsigned a3 = As[(rbase + g + 8) * AS2 + k2 + tig + 4];
#pragma unroll
        for (int j = 0; j < 8; j++) {
            unsigned b0 = Bs[(cbase + j * 8 + g) * AS2 + k2 + tig];
            unsigned b1 = Bs[(cbase + j * 8 + g) * AS2 + k2 + tig + 4];
            asm("mma.sync.aligned.m16n8k16.row.col.f32.f16.f16.f32 "
                "{%0,%1,%2,%3},{%4,%5,%6,%7},{%8,%9},{%0,%1,%2,%3};"
                : "+f"(acc[j][0]), "+f"(acc[j][1]), "+f"(acc[j][2]), "+f"(acc[j][3])
                : "r"(a0), "r"(a1), "r"(a2), "r"(a3), "r"(b0), "r"(b1));
        }
    }

    int r0g = row0 + rbase + g;
    int r1g = r0g + 8;
#pragma unroll
    for (int j = 0; j < 8; j++) {
        int c0 = cbase + j * 8 + tig * 2;
        float bb0 = bl[c0], bb1 = bl[c0 + 1];
        __half2 h0 = __floats2half2_rn(acc[j][0] + bb0, acc[j][1] + bb1);
        __half2 h1 = __floats2half2_rn(acc[j][2] + bb0, acc[j][3] + bb1);
        *(__half2*)&g_hl16[(size_t)r0g * DD + c0] = h0;
        *(__half2*)&g_hl16[(size_t)r1g * DD + c0] = h1;
    }
}

// ---------------- fused: aggregate (CSR by dest, no atomics) + BN stats ----------------
// agg[c] = relu(hl[c]+root)*invdeg + sum_{p in [off[c],off[c+1])} norm[p]*relu(hl[rows[p]]+ee[p])
// stats accumulated from fp32 registers; agg stored fp16
__global__ void k_msg_fused(const float* __restrict__ rootl) {
    int tid = threadIdx.x;
    int lane = tid & 31;
    int wraw = tid >> 5;
    int gw = blockIdx.x * 8 + wraw;
    const int TOTW = MSG_BLOCKS * 8;
    const int chunk = (NN + TOTW - 1) / TOTW;
    int c0 = gw * chunk;
    int c1 = c0 + chunk; if (c1 > NN) c1 = NN;

    float4 r4 = ((const float4*)rootl)[lane];
    float s0 = 0.f, s1 = 0.f, s2 = 0.f, s3 = 0.f;
    float q0 = 0.f, q1 = 0.f, q2 = 0.f, q3 = 0.f;
    const uint2* hl2 = (const uint2*)g_hl16;
    const uint2* ee2 = (const uint2*)g_ee16;
    uint2* agg2 = (uint2*)g_agg16;

    for (int c = c0; c < c1; c++) {
        float idg = g_invdeg[c];
        uint2 hraw = hl2[(size_t)c * 32 + lane];
        float2 f01 = __half22float2(*(__half2*)&hraw.x);
        float2 f23 = __half22float2(*(__half2*)&hraw.y);
        float4 o;
        o.x = fmaxf(f01.x + r4.x, 0.f) * idg;
        o.y = fmaxf(f01.y + r4.y, 0.f) * idg;
        o.z = fmaxf(f23.x + r4.z, 0.f) * idg;
        o.w = fmaxf(f23.y + r4.w, 0.f) * idg;
        int e0 = g_off[c], e1 = g_off[c + 1];
        for (int p = e0; p < e1; p++) {
            int r = g_rows[p];
            float nrm = g_norm[p];
            uint2 hh = hl2[(size_t)r * 32 + lane];
            uint2 em = ee2[(size_t)p * 32 + lane];
            float2 h01 = __half22float2(*(__half2*)&hh.x);
            float2 h23 = __half22float2(*(__half2*)&hh.y);
            float2 e01 = __half22float2(*(__half2*)&em.x);
            float2 e23 = __half22float2(*(__half2*)&em.y);
            o.x = fmaf(nrm, fmaxf(h01.x + e01.x, 0.f), o.x);
            o.y = fmaf(nrm, fmaxf(h01.y + e01.y, 0.f), o.y);
            o.z = fmaf(nrm, fmaxf(h23.x + e23.x, 0.f), o.z);
            o.w = fmaf(nrm, fmaxf(h23.y + e23.y, 0.f), o.w);
        }
        __half2 o01 = __floats2half2_rn(o.x, o.y);
        __half2 o23 = __floats2half2_rn(o.z, o.w);
        agg2[(size_t)c * 32 + lane] = make_uint2(*(unsigned*)&o01, *(unsigned*)&o23);
        s0 += o.x; s1 += o.y; s2 += o.z; s3 += o.w;
        q0 += o.x * o.x; q1 += o.y * o.y; q2 += o.z * o.z; q3 += o.w * o.w;
    }

    __shared__ float sh[256][4];
    sh[tid][0] = s0; sh[tid][1] = s1; sh[tid][2] = s2; sh[tid][3] = s3;
    __syncthreads();
    if (wraw == 0) {
        float t0 = 0.f, t1 = 0.f, t2 = 0.f, t3 = 0.f;
#pragma unroll
        for (int g = 0; g < 8; g++) {
            t0 += sh[g * 32 + lane][0];
            t1 += sh[g * 32 + lane][1];
            t2 += sh[g * 32 + lane][2];
            t3 += sh[g * 32 + lane][3];
        }
        atomicAdd(&g_sum[lane * 4 + 0], (double)t0);
        atomicAdd(&g_sum[lane * 4 + 1], (double)t1);
        atomicAdd(&g_sum[lane * 4 + 2], (double)t2);
        atomicAdd(&g_sum[lane * 4 + 3], (double)t3);
    }
    __syncthreads();
    sh[tid][0] = q0; sh[tid][1] = q1; sh[tid][2] = q2; sh[tid][3] = q3;
    __syncthreads();
    if (wraw == 0) {
        float t0 = 0.f, t1 = 0.f, t2 = 0.f, t3 = 0.f;
#pragma unroll
        for (int g = 0; g < 8; g++) {
            t0 += sh[g * 32 + lane][0];
            t1 += sh[g * 32 + lane][1];
            t2 += sh[g * 32 + lane][2];
            t3 += sh[g * 32 + lane][3];
        }
        atomicAdd(&g_sq[lane * 4 + 0], (double)t0);
        atomicAdd(&g_sq[lane * 4 + 1], (double)t1);
        atomicAdd(&g_sq[lane * 4 + 2], (double)t2);
        atomicAdd(&g_sq[lane * 4 + 3], (double)t3);
    }
}

__global__ void k_bn_prep(const float* __restrict__ gammal,
                          const float* __restrict__ betal) {
    int c = threadIdx.x;
    double mean = g_sum[c] / (double)NN;
    double var = g_sq[c] / (double)NN - mean * mean;
    if (var < 0.0) var = 0.0;
    float inv = rsqrtf((float)var + BN_EPS);
    float sc = gammal[c] * inv;
    g_scale[c] = sc;
    g_shift[c] = betal[c] - (float)mean * sc;
}

// final: out += h1..h4 + bn(agg_last) (no relu)
__global__ void k_total(float* __restrict__ out) {
    size_t idx = (size_t)blockIdx.x * blockDim.x + threadIdx.x;  // NN*32 4-channel groups
    int lane = idx & 31;
    uint2 a = ((const uint2*)g_agg16)[idx];
    float2 a01 = __half22float2(*(__half2*)&a.x);
    float2 a23 = __half22float2(*(__half2*)&a.y);
    float4 sc = ((const float4*)g_scale)[lane];
    float4 sf = ((const float4*)g_shift)[lane];
    float4 t = ((const float4*)out)[idx];
    t.x += fmaf(a01.x, sc.x, sf.x);
    t.y += fmaf(a01.y, sc.y, sf.y);
    t.z += fmaf(a23.x, sc.z, sf.z);
    t.w += fmaf(a23.y, sc.w, sf.w);
    const uint2* hb = (const uint2*)g_hbuf16;
    size_t stride = (size_t)NN * 32;
#pragma unroll
    for (int l = 0; l < 4; l++) {
        uint2 v = hb[idx + stride * l];
        float2 v01 = __half22float2(*(__half2*)&v.x);
        float2 v23 = __half22float2(*(__half2*)&v.y);
        t.x += v01.x; t.y += v01.y; t.z += v23.x; t.w += v23.y;
    }
    ((float4*)out)[idx] = t;
}

// ---------------- launch ----------------
extern "C" void kernel_launch(void* const* d_in, const int* in_sizes, int n_in,
                              void* d_out, int out_size) {
    const int*   x     = (const int*)d_in[0];
    const int*   ei    = (const int*)d_in[1];
    const int*   attr  = (const int*)d_in[2];
    const float* at    = (const float*)d_in[3];
    const float* bt    = (const float*)d_in[4];
    const float* W     = (const float*)d_in[5];
    const float* b     = (const float*)d_in[6];
    const float* root  = (const float*)d_in[7];
    const float* gamma = (const float*)d_in[8];
    const float* beta  = (const float*)d_in[9];
    float* out = (float*)d_out;

    cudaFuncSetAttribute(k_gemm<0>, cudaFuncAttributeMaxDynamicSharedMemorySize, GEMM_SMEM);
    cudaFuncSetAttribute(k_gemm<1>, cudaFuncAttributeMaxDynamicSharedMemorySize, GEMM_SMEM);

    k_node_enc<<<NN / 8, 256>>>(x, at, out);
    k_deg_init<<<(NN + 255) / 256, 256>>>();
    k_deg_count<<<(EE + 255) / 256, 256>>>(ei);
    k_dis<<<(NN + 255) / 256, 256>>>();
    k_scan1<<<SCAN_NBLK, SCAN_BLK>>>();
    k_scan2<<<1, SCAN_BLK>>>();
    k_scan3<<<(NN + 255) / 256, 256>>>();
    k_scatter<<<(EE + 255) / 256, 256>>>(ei);
    k_edge_enc<<<EE / 8, 256>>>(ei, attr, bt);

    __half* hbuf = (__half*)nullptr;
    cudaGetSymbolAddress((void**)&hbuf, g_hbuf16);
    for (int l = 0; l < LL; l++) {
        const float* Wl = W + (size_t)l * DD * DD;
        const float* bl = b + (size_t)l * DD;
        if (l == 0) {
            k_gemm<0><<<NN / 64, 256, GEMM_SMEM>>>(Wl, bl, nullptr);
        } else {
            k_gemm<1><<<NN / 64, 256, GEMM_SMEM>>>(Wl, bl,
                                                   hbuf + (size_t)(l - 1) * NN * DD);
        }
        k_msg_fused<<<MSG_BLOCKS, 256>>>(root + (size_t)l * DD);
        k_bn_prep<<<1, 128>>>(gamma + (size_t)l * DD, beta + (size_t)l * DD);
    }
    k_total<<<NN * 32 / 256, 256>>>(out);
}